// round 12
// baseline (speedup 1.0000x reference)
#include <cuda_runtime.h>
#include <math.h>
#include <float.h>

// WaveNet autoregressive generation, sm_103a — round 11: packed FFMA2.
// Structure = round-10 winner (64 CTAs x 2 rows; 384 thr = 256 main + 128
// lagged-skip; warp specialization). Change: every matvec uses packed
// fma.rn.f32x2 (2 fp32 FMAs per instruction, bit-identical numerics) with
// activations stored DUPLICATED-packed in smem so one LDS.128 feeds four
// FFMA2s with no pack MOVs. Halves the FMA-pipe instruction floor
// (1152 -> 576 cyc/layer). Partial-buffer bytes & reduce phases unchanged.

#define NLAYER 30
#define BB 128
#define VV 256
#define RING_PER_ROW 3069   // 3 * (2^10 - 1) slots, 64 floats each

__device__ float g_ring[(size_t)BB * RING_PER_ROW * 64];  // ~100.6 MB scratch

#define BAR_MAIN() asm volatile("bar.sync 1, 256;" ::: "memory")

typedef unsigned long long u64;

// packed d = a*b + d (2 x fp32 lanes, IEEE fma each)
__device__ __forceinline__ void fma2(u64& d, u64 a, u64 b) {
    asm("fma.rn.f32x2 %0, %1, %2, %0;" : "+l"(d) : "l"(a), "l"(b));
}

// duplicated-packed store: base[2i] = base[2i+1] = v
__device__ __forceinline__ void st_dup(float* base, int idx, float v) {
    *(float2*)(base + 2 * idx) = make_float2(v, v);
}

template<int N>
__device__ __forceinline__ void wload2(ulonglong2* dst,
                                       const ulonglong2* __restrict__ Wg, int s) {
#pragma unroll
    for (int u = 0; u < N; u++) dst[u] = Wg[(size_t)u * s];
}

// N k-steps (N even), both rows, weights in a register buffer (w[k] = one
// j-quad row as 2 packed pairs), acts duplicated-packed in smem.
template<int N>
__device__ __forceinline__ void mm2_reg(const ulonglong2* __restrict__ a0,
                                        const ulonglong2* __restrict__ a1,
                                        const ulonglong2* w,
                                        u64& o0a, u64& o0b, u64& o1a, u64& o1b) {
#pragma unroll
    for (int kk = 0; kk < N / 2; kk++) {
        ulonglong2 x0 = a0[kk], x1 = a1[kk];
        fma2(o0a, w[2*kk].x, x0.x);
        fma2(o0b, w[2*kk].y, x0.x);
        fma2(o1a, w[2*kk].x, x1.x);
        fma2(o1b, w[2*kk].y, x1.x);
        fma2(o0a, w[2*kk+1].x, x0.y);
        fma2(o0b, w[2*kk+1].y, x0.y);
        fma2(o1a, w[2*kk+1].x, x1.y);
        fma2(o1b, w[2*kk+1].y, x1.y);
    }
}

// N k-steps (N even) streaming weights from global.
template<int N>
__device__ __forceinline__ void mm2_gl(const ulonglong2* __restrict__ a0,
                                       const ulonglong2* __restrict__ a1,
                                       const ulonglong2* __restrict__ Wg, int s,
                                       u64& o0a, u64& o0b, u64& o1a, u64& o1b) {
#pragma unroll
    for (int kk = 0; kk < N / 2; kk++) {
        ulonglong2 w0 = Wg[(size_t)(2*kk) * s];
        ulonglong2 w1 = Wg[(size_t)(2*kk+1) * s];
        ulonglong2 x0 = a0[kk], x1 = a1[kk];
        fma2(o0a, w0.x, x0.x);
        fma2(o0b, w0.y, x0.x);
        fma2(o1a, w0.x, x1.x);
        fma2(o1b, w0.y, x1.x);
        fma2(o0a, w1.x, x0.y);
        fma2(o0b, w1.y, x0.y);
        fma2(o1a, w1.x, x1.y);
        fma2(o1b, w1.y, x1.y);
    }
}

__global__ __launch_bounds__(384, 1)
void wavenet_kernel(const int* __restrict__ seed,
                    const float* __restrict__ emb,     // (V, 64)
                    const float* __restrict__ kern,    // (L, 2, 64, 128)
                    const float* __restrict__ cbias,   // (L, 128)
                    const float* __restrict__ rw,      // (L, 64, 64)
                    const float* __restrict__ rb,      // (L, 64)
                    const float* __restrict__ sw,      // (L, 64, 256)
                    const float* __restrict__ sb,      // (L, 256)
                    const float* __restrict__ ow0,     // (256, 256)
                    const float* __restrict__ ob0,     // (256)
                    const float* __restrict__ ow1,     // (256, 256)
                    const float* __restrict__ ob1,     // (256)
                    float* __restrict__ out,
                    int T, long long samp_off, long long logit_off, int mode)
{
    // duplicated-packed activation buffers ([2i]==[2i+1])
    __shared__ __align__(16) float dx[2][128];          // current x
    __shared__ __align__(16) float dxl[2][128];         // x_last (queue pop)
    __shared__ __align__(16) float dgb[2][2][128];      // gate, double-buffered
    __shared__ __align__(16) float dsk[2][512];         // relu(skip)
    __shared__ __align__(16) float dh0[2][512];         // relu(h0)
    __shared__ __align__(16) float slg[2][256];         // logits (scalar)
    __shared__ __align__(16) float cbs[NLAYER * 128];   // staged conv bias
    __shared__ __align__(16) float ssb[256];            // sum of skip biases
    __shared__ __align__(16) float obs0[256], obs1[256];
    __shared__ __align__(16) float pbuf[3072];          // 12KB partials union
    __shared__ int snidx[2];

    float (*scp)[2][128] = (float(*)[2][128])pbuf;   // [8][2][128] conv
    float (*srp)[2][64]  = (float(*)[2][64])pbuf;    // [16][2][64] res
    float (*ssp)[2][256] = (float(*)[2][256])pbuf;   // [6][2][256] skip/head

    const int tid = threadIdx.x;
    const int row0 = blockIdx.x * 2;
    const bool is_main = tid < 256;

    // main mappings (identical to R10)
    const int jqc = tid & 31, ksc = tid >> 5, kbc = ksc * 8;   // conv 32jq x 8ks
    const int jqr = tid & 15, ksr = tid >> 4, kbr = ksr * 4;   // res  16jq x 16ks
    const int r = tid >> 6, c = tid & 63;                      // tid<128 combines
    const int ch = tid;                                        // tid<256 combines
    // head mapping over ALL 384 threads: 64jq x 6ks, k = {48,48,48,48,32,32}
    const int jqh = tid & 63, ksh = tid >> 6;
    const int khb = (ksh < 4) ? ksh * 48 : 192 + (ksh - 4) * 32;
    // skip-group mapping (tid >= 256): 64jq x 2ks of 32
    const int st = tid & 127;
    const int jqs = st & 63, kss = st >> 6, kbs = kss * 32;

    ulonglong2 wk[8];   // main: conv K0[0..3]|K1[4..7]; all: head rows
    ulonglong2 wr[4];   // main: res prefetch
    u64 osk0a = 0, osk0b = 0, osk1a = 0, osk1b = 0;  // skip accumulators
    float rpop = 0.f, rbv = 0.f;

    // ---- one-time staging ----
    for (int idx = tid; idx < NLAYER * 128; idx += 384) cbs[idx] = cbias[idx];
    if (tid < 256) {
        float s = 0.f;
#pragma unroll 1
        for (int i = 0; i < NLAYER; i++) s += sb[i * 256 + tid];
        ssb[tid] = s;
        obs0[tid] = ob0[tid];
        obs1[tid] = ob1[tid];
    }
    if (tid < 2) snidx[tid] = seed[row0 + tid];
    if (is_main) {   // prefetch conv (t=0, layer 0)
        wload2<4>(wk,     (const ulonglong2*)kern + (size_t)kbc * 32 + jqc,        32);
        wload2<4>(wk + 4, (const ulonglong2*)kern + (size_t)(64 + kbc) * 32 + jqc, 32);
    }
    __syncthreads();

#pragma unroll 1
    for (int t = 0; t < T; t++) {
        // ---- step head ----
        if (tid < 128) {
            float xv = emb[(size_t)snidx[r] * 64 + c];
            st_dup(dx[r], c, xv);
            st_dup(dxl[r], c, rpop);
        }
        if (!is_main) { osk0a = osk0b = osk1a = osk1b = 0ull; }

#pragma unroll 1
        for (int i = 0; i < NLAYER; i++) {
            __syncthreads();   // P_i: x_i ready; sg[i-1] ready; skip_{i-2} done

            if (is_main) {
                const int d = 1 << (i % 10);
                const long long off = (long long)(i / 10) * 1023 + (d - 1);

                // -- A: conv partials (4 pre + 4 stream per matrix) + push + rb + wr
                {
                    const ulonglong2* K0 = (const ulonglong2*)kern
                        + (size_t)(i * 2) * 64 * 32 + (size_t)kbc * 32 + jqc;
                    const ulonglong2* K1 = K0 + 64 * 32;
                    const ulonglong2* axl0 = (const ulonglong2*)&dxl[0][2 * kbc];
                    const ulonglong2* axl1 = (const ulonglong2*)&dxl[1][2 * kbc];
                    const ulonglong2* ax0  = (const ulonglong2*)&dx[0][2 * kbc];
                    const ulonglong2* ax1  = (const ulonglong2*)&dx[1][2 * kbc];
                    u64 o0a = 0, o0b = 0, o1a = 0, o1b = 0;
                    mm2_reg<4>(axl0,     axl1,     wk,     o0a, o0b, o1a, o1b);
                    mm2_gl<4> (axl0 + 2, axl1 + 2, K0 + 4 * 32, 32, o0a, o0b, o1a, o1b);
                    mm2_reg<4>(ax0,      ax1,      wk + 4, o0a, o0b, o1a, o1b);
                    mm2_gl<4> (ax0 + 2,  ax1 + 2,  K1 + 4 * 32, 32, o0a, o0b, o1a, o1b);
                    ulonglong2 s0; s0.x = o0a; s0.y = o0b;
                    ulonglong2 s1; s1.x = o1a; s1.y = o1b;
                    *(ulonglong2*)&scp[ksc][0][4 * jqc] = s0;
                    *(ulonglong2*)&scp[ksc][1][4 * jqc] = s1;
                }
                if (tid < 128) {
                    size_t idx = ((size_t)(row0 + r) * RING_PER_ROW + (size_t)off
                                  + (t & (d - 1))) * 64 + c;
                    g_ring[idx] = dx[r][2 * c];
                    rbv = rb[i * 64 + c];         // consumed in Phase D
                }
                wload2<4>(wr, (const ulonglong2*)rw + (size_t)i * 64 * 16
                              + (size_t)kbr * 16 + jqr, 16);
                BAR_MAIN();

                // -- B: gate -> dgb[i&1]; prefetch next conv + next pop
                if (i < NLAYER - 1) {
                    const ulonglong2* KN = (const ulonglong2*)kern
                        + (size_t)((i + 1) * 2) * 64 * 32;
                    wload2<4>(wk,     KN + (size_t)kbc * 32 + jqc,        32);
                    wload2<4>(wk + 4, KN + (size_t)(64 + kbc) * 32 + jqc, 32);
                    if (tid < 128) {
                        const int d2 = 1 << ((i + 1) % 10);
                        const long long off2 = (long long)((i + 1) / 10) * 1023 + (d2 - 1);
                        size_t idx2 = ((size_t)(row0 + r) * RING_PER_ROW + (size_t)off2
                                       + (t & (d2 - 1))) * 64 + c;
                        rpop = (t >= d2) ? g_ring[idx2] : 0.f;
                    }
                }
                if (tid < 128) {
                    float p0 = scp[0][r][c], p1 = scp[1][r][c];
                    float p2 = scp[2][r][c], p3 = scp[3][r][c];
                    float p4 = scp[4][r][c], p5 = scp[5][r][c];
                    float p6 = scp[6][r][c], p7 = scp[7][r][c];
                    float q0 = scp[0][r][c+64], q1 = scp[1][r][c+64];
                    float q2 = scp[2][r][c+64], q3 = scp[3][r][c+64];
                    float q4 = scp[4][r][c+64], q5 = scp[5][r][c+64];
                    float q6 = scp[6][r][c+64], q7 = scp[7][r][c+64];
                    float ht = (((p0+p1)+(p2+p3)) + ((p4+p5)+(p6+p7))) + cbs[i*128 + c];
                    float hs = (((q0+q1)+(q2+q3)) + ((q4+q5)+(q6+q7))) + cbs[i*128 + 64 + c];
                    float e2 = __expf(2.f * ht);
                    float th = 1.f - __fdividef(2.f, e2 + 1.f);
                    float sig = __fdividef(1.f, 1.f + __expf(-hs));
                    st_dup(dgb[i & 1][r], c, th * sig);
                }
                BAR_MAIN();

                // -- C: res partials (fully prefetched)
                {
                    const ulonglong2* ag0 = (const ulonglong2*)&dgb[i & 1][0][2 * kbr];
                    const ulonglong2* ag1 = (const ulonglong2*)&dgb[i & 1][1][2 * kbr];
                    u64 o0a = 0, o0b = 0, o1a = 0, o1b = 0;
                    mm2_reg<4>(ag0, ag1, wr, o0a, o0b, o1a, o1b);
                    ulonglong2 s0; s0.x = o0a; s0.y = o0b;
                    ulonglong2 s1; s1.x = o1a; s1.y = o1b;
                    *(ulonglong2*)&srp[ksr][0][4 * jqr] = s0;
                    *(ulonglong2*)&srp[ksr][1][4 * jqr] = s1;
                }
                BAR_MAIN();

                // -- D: x combine (tree-16) + stage next x_last
                if (tid < 128) {
                    float a0 = srp[0][r][c] + srp[1][r][c];
                    float a1 = srp[2][r][c] + srp[3][r][c];
                    float a2 = srp[4][r][c] + srp[5][r][c];
                    float a3 = srp[6][r][c] + srp[7][r][c];
                    float a4 = srp[8][r][c] + srp[9][r][c];
                    float a5 = srp[10][r][c] + srp[11][r][c];
                    float a6 = srp[12][r][c] + srp[13][r][c];
                    float a7 = srp[14][r][c] + srp[15][r][c];
                    float v = dx[r][2 * c] + rbv
                            + (((a0+a1)+(a2+a3)) + ((a4+a5)+(a6+a7)));
                    st_dup(dx[r], c, v);
                    if (i < NLAYER - 1) st_dup(dxl[r], c, rpop);
                }
            } else {
                // ---- skip group: lagged skip matmul of layer i-1 ----
                if (i > 0) {
                    const ulonglong2* SW = (const ulonglong2*)sw
                        + ((size_t)(i - 1) * 64 + kbs) * 64 + jqs;
                    const ulonglong2* ag0 =
                        (const ulonglong2*)&dgb[(i - 1) & 1][0][2 * kbs];
                    const ulonglong2* ag1 =
                        (const ulonglong2*)&dgb[(i - 1) & 1][1][2 * kbs];
                    mm2_gl<32>(ag0, ag1, SW, 64, osk0a, osk0b, osk1a, osk1b);
                }
            }
        }
        __syncthreads();   // P_30: layer 29 gate + combine done

        // ---- tail: skip_29 (skip group) while everyone prefetches head W0 ----
        wload2<8>(wk, (const ulonglong2*)ow0 + (size_t)khb * 64 + jqh, 64);
        if (!is_main) {
            const ulonglong2* SW = (const ulonglong2*)sw
                + ((size_t)(NLAYER - 1) * 64 + kbs) * 64 + jqs;
            const ulonglong2* ag0 =
                (const ulonglong2*)&dgb[(NLAYER - 1) & 1][0][2 * kbs];
            const ulonglong2* ag1 =
                (const ulonglong2*)&dgb[(NLAYER - 1) & 1][1][2 * kbs];
            mm2_gl<32>(ag0, ag1, SW, 64, osk0a, osk0b, osk1a, osk1b);
            ulonglong2 s0; s0.x = osk0a; s0.y = osk0b;
            ulonglong2 s1; s1.x = osk1a; s1.y = osk1b;
            *(ulonglong2*)&ssp[kss][0][4 * jqs] = s0;
            *(ulonglong2*)&ssp[kss][1][4 * jqs] = s1;
        }
        __syncthreads();

        // ---- skip combine + Σbias + relu -> duplicated dsk ----
        if (is_main) {
            float v0 = ssb[ch] + ssp[0][0][ch] + ssp[1][0][ch];
            float v1 = ssb[ch] + ssp[0][1][ch] + ssp[1][1][ch];
            st_dup(dsk[0], ch, fmaxf(v0, 0.f));
            st_dup(dsk[1], ch, fmaxf(v1, 0.f));
        }
        __syncthreads();

        // ---- head m0: h0 = relu(skip @ ow0 + ob0); all 384 threads ----
        {
            const ulonglong2* W = (const ulonglong2*)ow0 + (size_t)khb * 64 + jqh;
            const ulonglong2* a0 = (const ulonglong2*)&dsk[0][2 * khb];
            const ulonglong2* a1 = (const ulonglong2*)&dsk[1][2 * khb];
            u64 o0a = 0, o0b = 0, o1a = 0, o1b = 0;
            mm2_reg<8>(a0, a1, wk, o0a, o0b, o1a, o1b);
            if (ksh < 4)
                mm2_gl<40>(a0 + 4, a1 + 4, W + 8 * 64, 64, o0a, o0b, o1a, o1b);
            else
                mm2_gl<24>(a0 + 4, a1 + 4, W + 8 * 64, 64, o0a, o0b, o1a, o1b);
            wload2<8>(wk, (const ulonglong2*)ow1 + (size_t)khb * 64 + jqh, 64);
            ulonglong2 s0; s0.x = o0a; s0.y = o0b;
            ulonglong2 s1; s1.x = o1a; s1.y = o1b;
            *(ulonglong2*)&ssp[ksh][0][4 * jqh] = s0;
            *(ulonglong2*)&ssp[ksh][1][4 * jqh] = s1;
        }
        __syncthreads();
        if (is_main) {
            float v0 = obs0[ch] + (((ssp[0][0][ch] + ssp[1][0][ch])
                                  + (ssp[2][0][ch] + ssp[3][0][ch]))
                                  + (ssp[4][0][ch] + ssp[5][0][ch]));
            float v1 = obs0[ch] + (((ssp[0][1][ch] + ssp[1][1][ch])
                                  + (ssp[2][1][ch] + ssp[3][1][ch]))
                                  + (ssp[4][1][ch] + ssp[5][1][ch]));
            st_dup(dh0[0], ch, fmaxf(v0, 0.f));
            st_dup(dh0[1], ch, fmaxf(v1, 0.f));
        }
        __syncthreads();

        // ---- head m1: logits = h0 @ ow1 + ob1; all 384 threads ----
        {
            const ulonglong2* W = (const ulonglong2*)ow1 + (size_t)khb * 64 + jqh;
            const ulonglong2* a0 = (const ulonglong2*)&dh0[0][2 * khb];
            const ulonglong2* a1 = (const ulonglong2*)&dh0[1][2 * khb];
            u64 o0a = 0, o0b = 0, o1a = 0, o1b = 0;
            mm2_reg<8>(a0, a1, wk, o0a, o0b, o1a, o1b);
            if (ksh < 4)
                mm2_gl<40>(a0 + 4, a1 + 4, W + 8 * 64, 64, o0a, o0b, o1a, o1b);
            else
                mm2_gl<24>(a0 + 4, a1 + 4, W + 8 * 64, 64, o0a, o0b, o1a, o1b);
            // prefetch (t+1, layer 0) conv weights + layer-0 pop
            if (is_main) {
                wload2<4>(wk,     (const ulonglong2*)kern + (size_t)kbc * 32 + jqc,        32);
                wload2<4>(wk + 4, (const ulonglong2*)kern + (size_t)(64 + kbc) * 32 + jqc, 32);
            }
            if (tid < 128)
                rpop = g_ring[((size_t)(row0 + r) * RING_PER_ROW) * 64 + c];
            ulonglong2 s0; s0.x = o0a; s0.y = o0b;
            ulonglong2 s1; s1.x = o1a; s1.y = o1b;
            *(ulonglong2*)&ssp[ksh][0][4 * jqh] = s0;
            *(ulonglong2*)&ssp[ksh][1][4 * jqh] = s1;
        }
        __syncthreads();
        if (is_main) {
            float v0 = obs1[ch] + (((ssp[0][0][ch] + ssp[1][0][ch])
                                  + (ssp[2][0][ch] + ssp[3][0][ch]))
                                  + (ssp[4][0][ch] + ssp[5][0][ch]));
            float v1 = obs1[ch] + (((ssp[0][1][ch] + ssp[1][1][ch])
                                  + (ssp[2][1][ch] + ssp[3][1][ch]))
                                  + (ssp[4][1][ch] + ssp[5][1][ch]));
            slg[0][ch] = v0;
            slg[1][ch] = v1;
            if (mode & 2) {
                out[logit_off + ((size_t)(row0 + 0) * T + t) * VV + ch] = v0;
                out[logit_off + ((size_t)(row0 + 1) * T + t) * VV + ch] = v1;
            }
        }
        __syncthreads();

        // ---- argmax per row (first-max tie rule, matches jnp.argmax) ----
        if (tid < 64) {
            int rr = tid >> 5, lane = tid & 31;
            float bv = -FLT_MAX;
            int bi = 0;
#pragma unroll
            for (int jj = 0; jj < 8; jj++) {
                int j = lane + jj * 32;
                float v = slg[rr][j];
                if (v > bv) { bv = v; bi = j; }
            }
#pragma unroll
            for (int o2 = 16; o2 > 0; o2 >>= 1) {
                float ov = __shfl_down_sync(0xffffffffu, bv, o2);
                int   oi = __shfl_down_sync(0xffffffffu, bi, o2);
                if (ov > bv || (ov == bv && oi < bi)) { bv = ov; bi = oi; }
            }
            if (lane == 0) {
                snidx[rr] = bi;
                if (mode & 1) out[samp_off + (size_t)(row0 + rr) * T + t] = (float)bi;
                if (mode & 4) ((int*)out)[(size_t)(row0 + rr) * T + t] = bi;
            }
        }
        __syncthreads();
    }
}

extern "C" void kernel_launch(void* const* d_in, const int* in_sizes, int n_in,
                              void* d_out, int out_size) {
    const int*   seed  = (const int*)d_in[0];
    const float* emb   = (const float*)d_in[1];
    const float* kern  = (const float*)d_in[2];
    const float* cbias = (const float*)d_in[3];
    const float* rw    = (const float*)d_in[4];
    const float* rb    = (const float*)d_in[5];
    const float* sw    = (const float*)d_in[6];
    const float* sb    = (const float*)d_in[7];
    const float* ow0   = (const float*)d_in[8];
    const float* ob0   = (const float*)d_in[9];
    const float* ow1   = (const float*)d_in[10];
    const float* ob1   = (const float*)d_in[11];
    (void)in_sizes; (void)n_in;

    int T, mode;
    long long samp_off = 0, logit_off = 0;
    if (out_size % (BB * (VV + 1)) == 0) {
        T = out_size / (BB * (VV + 1));
        mode = 1 | 2;                       // float samples then logits
        samp_off = 0;
        logit_off = (long long)BB * T;
    } else if (out_size % (BB * VV) == 0) {
        T = out_size / (BB * VV);
        mode = 2;                           // logits only
        logit_off = 0;
    } else {
        T = out_size / BB;
        mode = 4;                           // int32 samples only
    }

    wavenet_kernel<<<BB / 2, 384>>>(seed, emb, kern, cbias, rw, rb, sw, sb,
                                    ow0, ob0, ow1, ob1,
                                    (float*)d_out, T, samp_off, logit_off, mode);
}

// round 13
// speedup vs baseline: 1.1619x; 1.1619x over previous
#include <cuda_runtime.h>
#include <math.h>
#include <float.h>

// WaveNet autoregressive generation, sm_103a — round 12: 128 CTAs x 1 row.
// Structure = round-10 winner (warp specialization: 256 main threads run
// conv/gate/res, 128 skip threads run the lagged skip matmul), but each CTA
// now owns ONE batch row: per-CTA FMA work halves while the weight-load
// stream (same L2 addresses chip-wide) and barrier count stay fixed.
// Evidence basis: R10 profile showed L2=29.8% (headroom) and 84 idle SMs.

#define NLAYER 30
#define BB 128
#define VV 256
#define RING_PER_ROW 3069   // 3 * (2^10 - 1) slots, 64 floats each

__device__ float g_ring[(size_t)BB * RING_PER_ROW * 64];  // ~100.6 MB scratch

#define BAR_MAIN() asm volatile("bar.sync 1, 256;" ::: "memory")

template<int N>
__device__ __forceinline__ void wload(float4* dst, const float4* __restrict__ Wg,
                                      int s4) {
#pragma unroll
    for (int u = 0; u < N; u++) dst[u] = Wg[(size_t)u * s4];
}

// FMA N k-steps (N%4==0), one row, weights from a register buffer.
template<int N>
__device__ __forceinline__ void mm_reg(const float* __restrict__ a0,
                                       const float4* w, float4& o0) {
#pragma unroll
    for (int c2 = 0; c2 < N; c2 += 4) {
        float v0[4];
        *(float4*)v0 = *(const float4*)(a0 + c2);
#pragma unroll
        for (int u = 0; u < 4; u++) {
            const float4 wv = w[c2 + u];
            o0.x = fmaf(v0[u], wv.x, o0.x);
            o0.y = fmaf(v0[u], wv.y, o0.y);
            o0.z = fmaf(v0[u], wv.z, o0.z);
            o0.w = fmaf(v0[u], wv.w, o0.w);
        }
    }
}

// FMA N k-steps streaming weights from global (independent LDGs pipeline).
template<int N>
__device__ __forceinline__ void mm_gl(const float* __restrict__ a0,
                                      const float4* __restrict__ Wg, int s4,
                                      float4& o0) {
#pragma unroll
    for (int c2 = 0; c2 < N; c2 += 4) {
        float v0[4];
        *(float4*)v0 = *(const float4*)(a0 + c2);
#pragma unroll
        for (int u = 0; u < 4; u++) {
            const float4 wv = Wg[(size_t)(c2 + u) * s4];
            o0.x = fmaf(v0[u], wv.x, o0.x);
            o0.y = fmaf(v0[u], wv.y, o0.y);
            o0.z = fmaf(v0[u], wv.z, o0.z);
            o0.w = fmaf(v0[u], wv.w, o0.w);
        }
    }
}

__global__ __launch_bounds__(384, 1)
void wavenet_kernel(const int* __restrict__ seed,
                    const float* __restrict__ emb,     // (V, 64)
                    const float* __restrict__ kern,    // (L, 2, 64, 128)
                    const float* __restrict__ cbias,   // (L, 128)
                    const float* __restrict__ rw,      // (L, 64, 64)
                    const float* __restrict__ rb,      // (L, 64)
                    const float* __restrict__ sw,      // (L, 64, 256)
                    const float* __restrict__ sb,      // (L, 256)
                    const float* __restrict__ ow0,     // (256, 256)
                    const float* __restrict__ ob0,     // (256)
                    const float* __restrict__ ow1,     // (256, 256)
                    const float* __restrict__ ob1,     // (256)
                    float* __restrict__ out,
                    int T, long long samp_off, long long logit_off, int mode)
{
    __shared__ __align__(16) float sx[64];
    __shared__ __align__(16) float sxl[64];
    __shared__ __align__(16) float sgb[2][64];          // double-buffered gate
    __shared__ __align__(16) float ssk[256];
    __shared__ __align__(16) float sh0[256];
    __shared__ __align__(16) float slg[256];
    __shared__ __align__(16) float cbs[NLAYER * 128];   // staged conv bias
    __shared__ __align__(16) float ssb[256];            // sum of skip biases
    __shared__ __align__(16) float obs0[256], obs1[256];
    __shared__ __align__(16) float pbuf[1536];          // 6KB partials union
    __shared__ int snidx;

    float (*scp)[128] = (float(*)[128])pbuf;   // [8][128] conv
    float (*srp)[64]  = (float(*)[64])pbuf;    // [16][64] res
    float (*ssp)[256] = (float(*)[256])pbuf;   // [6][256] skip/head

    const int tid = threadIdx.x;
    const int row = blockIdx.x;
    const bool is_main = tid < 256;

    // main mappings
    const int jqc = tid & 31, ksc = tid >> 5, kbc = ksc * 8;   // conv 32jq x 8ks
    const int jqr = tid & 15, ksr = tid >> 4, kbr = ksr * 4;   // res  16jq x 16ks
    const int c = tid;                                         // tid<64 scalar
    const int ch = tid;                                        // tid<256 combines
    // head mapping over ALL 384 threads: 64jq x 6ks, k = {48,48,48,48,32,32}
    const int jqh = tid & 63, ksh = tid >> 6;
    const int khb = (ksh < 4) ? ksh * 48 : 192 + (ksh - 4) * 32;
    // skip-group mapping (tid >= 256): 64jq x 2ks of 32
    const int st = tid & 127;
    const int jqs = st & 63, kss = st >> 6, kbs = kss * 32;

    float4 wk[8];   // main: conv K0[0..3]|K1[4..7]; all: head rows khb..khb+7
    float4 wr[4];   // main: res prefetch
    float4 osk = {0, 0, 0, 0};  // skip-group accumulator
    float  rpop = 0.f, rbv = 0.f;

    // ---- one-time staging ----
    for (int idx = tid; idx < NLAYER * 128; idx += 384) cbs[idx] = cbias[idx];
    if (tid < 256) {
        float s = 0.f;
#pragma unroll 1
        for (int i = 0; i < NLAYER; i++) s += sb[i * 256 + tid];
        ssb[tid] = s;
        obs0[tid] = ob0[tid];
        obs1[tid] = ob1[tid];
    }
    if (tid == 0) snidx = seed[row];
    if (is_main) {   // prefetch conv (t=0, layer 0)
        wload<4>(wk,     (const float4*)kern + (size_t)kbc * 32 + jqc,        32);
        wload<4>(wk + 4, (const float4*)kern + (size_t)(64 + kbc) * 32 + jqc, 32);
    }
    __syncthreads();

#pragma unroll 1
    for (int t = 0; t < T; t++) {
        // ---- step head ----
        if (tid < 64) {
            sx[c] = emb[(size_t)snidx * 64 + c];
            sxl[c] = rpop;
        }
        if (!is_main) { osk.x = osk.y = osk.z = osk.w = 0.f; }

#pragma unroll 1
        for (int i = 0; i < NLAYER; i++) {
            __syncthreads();   // P_i: sx_i ready; sg[i-1] ready; skip_{i-2} done

            if (is_main) {
                const int d = 1 << (i % 10);
                const long long off = (long long)(i / 10) * 1023 + (d - 1);

                // -- A: conv partials (4 pre + 4 stream per matrix) + push + rb + wr
                {
                    const float4* K0 = (const float4*)kern
                        + (size_t)(i * 2) * 64 * 32 + (size_t)kbc * 32 + jqc;
                    const float4* K1 = K0 + 64 * 32;
                    float4 o0 = {0, 0, 0, 0};
                    mm_reg<4>(sxl + kbc,     wk,          o0);
                    mm_gl<4> (sxl + kbc + 4, K0 + 4 * 32, 32, o0);
                    mm_reg<4>(sx + kbc,      wk + 4,      o0);
                    mm_gl<4> (sx + kbc + 4,  K1 + 4 * 32, 32, o0);
                    *(float4*)&scp[ksc][4 * jqc] = o0;
                }
                if (tid < 64) {
                    size_t idx = ((size_t)row * RING_PER_ROW + (size_t)off
                                  + (t & (d - 1))) * 64 + c;
                    g_ring[idx] = sx[c];
                    rbv = rb[i * 64 + c];         // consumed in Phase D
                }
                wload<4>(wr, (const float4*)rw + (size_t)i * 64 * 16
                             + (size_t)kbr * 16 + jqr, 16);
                BAR_MAIN();

                // -- B: gate -> sg[i&1]; prefetch next conv + next pop
                if (i < NLAYER - 1) {
                    const float4* KN = (const float4*)kern
                        + (size_t)((i + 1) * 2) * 64 * 32;
                    wload<4>(wk,     KN + (size_t)kbc * 32 + jqc,        32);
                    wload<4>(wk + 4, KN + (size_t)(64 + kbc) * 32 + jqc, 32);
                    if (tid < 64) {
                        const int d2 = 1 << ((i + 1) % 10);
                        const long long off2 = (long long)((i + 1) / 10) * 1023 + (d2 - 1);
                        size_t idx2 = ((size_t)row * RING_PER_ROW + (size_t)off2
                                       + (t & (d2 - 1))) * 64 + c;
                        rpop = (t >= d2) ? g_ring[idx2] : 0.f;
                    }
                }
                if (tid < 64) {
                    float p0 = scp[0][c], p1 = scp[1][c];
                    float p2 = scp[2][c], p3 = scp[3][c];
                    float p4 = scp[4][c], p5 = scp[5][c];
                    float p6 = scp[6][c], p7 = scp[7][c];
                    float q0 = scp[0][c+64], q1 = scp[1][c+64];
                    float q2 = scp[2][c+64], q3 = scp[3][c+64];
                    float q4 = scp[4][c+64], q5 = scp[5][c+64];
                    float q6 = scp[6][c+64], q7 = scp[7][c+64];
                    float ht = (((p0+p1)+(p2+p3)) + ((p4+p5)+(p6+p7))) + cbs[i*128 + c];
                    float hs = (((q0+q1)+(q2+q3)) + ((q4+q5)+(q6+q7))) + cbs[i*128 + 64 + c];
                    float e2 = __expf(2.f * ht);
                    float th = 1.f - __fdividef(2.f, e2 + 1.f);
                    float sig = __fdividef(1.f, 1.f + __expf(-hs));
                    sgb[i & 1][c] = th * sig;
                }
                BAR_MAIN();

                // -- C: res partials (fully prefetched)
                {
                    float4 o0 = {0, 0, 0, 0};
                    mm_reg<4>(sgb[i & 1] + kbr, wr, o0);
                    *(float4*)&srp[ksr][4 * jqr] = o0;
                }
                BAR_MAIN();

                // -- D: x combine (tree-16) + stage next sxl
                if (tid < 64) {
                    float a0 = srp[0][c] + srp[1][c];
                    float a1 = srp[2][c] + srp[3][c];
                    float a2 = srp[4][c] + srp[5][c];
                    float a3 = srp[6][c] + srp[7][c];
                    float a4 = srp[8][c] + srp[9][c];
                    float a5 = srp[10][c] + srp[11][c];
                    float a6 = srp[12][c] + srp[13][c];
                    float a7 = srp[14][c] + srp[15][c];
                    float v = sx[c] + rbv
                            + (((a0+a1)+(a2+a3)) + ((a4+a5)+(a6+a7)));
                    sx[c] = v;
                    if (i < NLAYER - 1) sxl[c] = rpop;
                }
            } else {
                // ---- skip group: skip matmul of layer i-1 (reads sg[(i-1)&1],
                //      which main is not writing this iteration) ----
                if (i > 0) {
                    const float4* SW = (const float4*)sw
                        + ((size_t)(i - 1) * 64 + kbs) * 64 + jqs;
                    mm_gl<32>(sgb[(i - 1) & 1] + kbs, SW, 64, osk);
                }
            }
        }
        __syncthreads();   // P_30: layer 29 gate + combine done

        // ---- tail: skip_29 (skip group) while everyone prefetches head W0 ----
        wload<8>(wk, (const float4*)ow0 + (size_t)khb * 64 + jqh, 64);
        if (!is_main) {
            const float4* SW = (const float4*)sw
                + ((size_t)(NLAYER - 1) * 64 + kbs) * 64 + jqs;
            mm_gl<32>(sgb[(NLAYER - 1) & 1] + kbs, SW, 64, osk);
            *(float4*)&ssp[kss][4 * jqs] = osk;
        }
        __syncthreads();

        // ---- skip combine + Σbias + relu ----
        if (is_main) {
            float v0 = ssb[ch] + ssp[0][ch] + ssp[1][ch];
            ssk[ch] = fmaxf(v0, 0.f);
        }
        __syncthreads();

        // ---- head m0: h0 = relu(skip @ ow0 + ob0); all 384 threads ----
        {
            const float4* W = (const float4*)ow0 + (size_t)khb * 64 + jqh;
            float4 o0 = {0, 0, 0, 0};
            mm_reg<8>(ssk + khb, wk, o0);
            if (ksh < 4)
                mm_gl<40>(ssk + khb + 8, W + 8 * 64, 64, o0);
            else
                mm_gl<24>(ssk + khb + 8, W + 8 * 64, 64, o0);
            wload<8>(wk, (const float4*)ow1 + (size_t)khb * 64 + jqh, 64);
            *(float4*)&ssp[ksh][4 * jqh] = o0;
        }
        __syncthreads();
        if (is_main) {
            float v0 = obs0[ch] + (((ssp[0][ch] + ssp[1][ch])
                                  + (ssp[2][ch] + ssp[3][ch]))
                                  + (ssp[4][ch] + ssp[5][ch]));
            sh0[ch] = fmaxf(v0, 0.f);
        }
        __syncthreads();

        // ---- head m1: logits = h0 @ ow1 + ob1; all 384 threads ----
        {
            const float4* W = (const float4*)ow1 + (size_t)khb * 64 + jqh;
            float4 o0 = {0, 0, 0, 0};
            mm_reg<8>(sh0 + khb, wk, o0);
            if (ksh < 4)
                mm_gl<40>(sh0 + khb + 8, W + 8 * 64, 64, o0);
            else
                mm_gl<24>(sh0 + khb + 8, W + 8 * 64, 64, o0);
            // prefetch (t+1, layer 0) conv weights + layer-0 pop
            if (is_main) {
                wload<4>(wk,     (const float4*)kern + (size_t)kbc * 32 + jqc,        32);
                wload<4>(wk + 4, (const float4*)kern + (size_t)(64 + kbc) * 32 + jqc, 32);
            }
            if (tid < 64)
                rpop = g_ring[((size_t)row * RING_PER_ROW) * 64 + c];
            *(float4*)&ssp[ksh][4 * jqh] = o0;
        }
        __syncthreads();
        if (is_main) {
            float v0 = obs1[ch] + (((ssp[0][ch] + ssp[1][ch])
                                  + (ssp[2][ch] + ssp[3][ch]))
                                  + (ssp[4][ch] + ssp[5][ch]));
            slg[ch] = v0;
            if (mode & 2)
                out[logit_off + ((size_t)row * T + t) * VV + ch] = v0;
        }
        __syncthreads();

        // ---- argmax (first-max tie rule, matches jnp.argmax) ----
        if (tid < 32) {
            float bv = -FLT_MAX;
            int bi = 0;
#pragma unroll
            for (int jj = 0; jj < 8; jj++) {
                int j = tid + jj * 32;
                float v = slg[j];
                if (v > bv) { bv = v; bi = j; }
            }
#pragma unroll
            for (int o2 = 16; o2 > 0; o2 >>= 1) {
                float ov = __shfl_down_sync(0xffffffffu, bv, o2);
                int   oi = __shfl_down_sync(0xffffffffu, bi, o2);
                if (ov > bv || (ov == bv && oi < bi)) { bv = ov; bi = oi; }
            }
            if (tid == 0) {
                snidx = bi;
                if (mode & 1) out[samp_off + (size_t)row * T + t] = (float)bi;
                if (mode & 4) ((int*)out)[(size_t)row * T + t] = bi;
            }
        }
        __syncthreads();
    }
}

extern "C" void kernel_launch(void* const* d_in, const int* in_sizes, int n_in,
                              void* d_out, int out_size) {
    const int*   seed  = (const int*)d_in[0];
    const float* emb   = (const float*)d_in[1];
    const float* kern  = (const float*)d_in[2];
    const float* cbias = (const float*)d_in[3];
    const float* rw    = (const float*)d_in[4];
    const float* rb    = (const float*)d_in[5];
    const float* sw    = (const float*)d_in[6];
    const float* sb    = (const float*)d_in[7];
    const float* ow0   = (const float*)d_in[8];
    const float* ob0   = (const float*)d_in[9];
    const float* ow1   = (const float*)d_in[10];
    const float* ob1   = (const float*)d_in[11];
    (void)in_sizes; (void)n_in;

    int T, mode;
    long long samp_off = 0, logit_off = 0;
    if (out_size % (BB * (VV + 1)) == 0) {
        T = out_size / (BB * (VV + 1));
        mode = 1 | 2;                       // float samples then logits
        samp_off = 0;
        logit_off = (long long)BB * T;
    } else if (out_size % (BB * VV) == 0) {
        T = out_size / (BB * VV);
        mode = 2;                           // logits only
        logit_off = 0;
    } else {
        T = out_size / BB;
        mode = 4;                           // int32 samples only
    }

    wavenet_kernel<<<BB, 384>>>(seed, emb, kern, cbias, rw, rb, sw, sb,
                                ow0, ob0, ow1, ob1,
                                (float*)d_out, T, samp_off, logit_off, mode);
}